// round 9
// baseline (speedup 1.0000x reference)
#include <cuda_runtime.h>

// Residual quantization, N=65536, D=128, M=8, K=256.
// v7: maximize the tile harmonic kk*v/(kk+v) — the measured LDS:FMA balance
// knob (v4=3.2/53.6% fma, v5=2.0/52.9%, v6=1.6/42.4%). kk=8, v=8 gives 4.0,
// i.e. 4(kk+v) == kk*v: LDS crossbar demand == FMA issue demand (balanced).
// acc = 64 u64 = 128 regs -> needs full 255-reg budget -> 1 CTA x 256 threads.
// VB=128 (ty16 x v8), grid=512; SROWS=128 (two 64KB ping-pong buffers,
// 2 segments/stage), cp.async depth-2; norms precomputed; epilogue winner row
// from global cb (L2-hot).

#define NV 65536
#define DD 128
#define MS 8
#define KC 256
#define TPB 256
#define VB 128                    // vectors per block
#define RPAD 132                  // residual row stride (floats)
#define SROWS 128                 // codewords per segment
#define SFLOATS (SROWS * DD)      // 16384 floats = 64KB per buffer
#define NSEG (MS * KC / SROWS)    // 16 linear segments
#define SMEM_FLOATS (2 * SFLOATS + VB * RPAD + MS * KC)
#define SMEM_BYTES (SMEM_FLOATS * 4)

typedef unsigned long long u64;

__device__ float g_norms[MS * KC];

__device__ __forceinline__ void upk2(u64 v, float& lo, float& hi) {
    asm("mov.b64 {%0, %1}, %2;" : "=f"(lo), "=f"(hi) : "l"(v));
}
// Packed dual-fp32 FMA (Blackwell FFMA2), PTX-only.
__device__ __forceinline__ void ffma2(u64& d, u64 a, u64 b) {
    asm("fma.rn.f32x2 %0, %1, %2, %0;" : "+l"(d) : "l"(a), "l"(b));
}
__device__ __forceinline__ void cp16(float* dst_smem, const float* src_gmem) {
    unsigned s = (unsigned)__cvta_generic_to_shared(dst_smem);
    asm volatile("cp.async.cg.shared.global [%0], [%1], 16;" :: "r"(s), "l"(src_gmem));
}

// ---- norms: one thread per (stage, codeword) ----
__global__ void norms_kernel(const float* __restrict__ cb) {
    int m = blockIdx.x, k = threadIdx.x;
    const float4* row = (const float4*)(cb + ((size_t)m * KC + k) * DD);
    float s = 0.f;
    #pragma unroll
    for (int j = 0; j < 32; ++j) {
        float4 v = row[j];
        s = fmaf(v.x, v.x, s); s = fmaf(v.y, v.y, s);
        s = fmaf(v.z, v.z, s); s = fmaf(v.w, v.w, s);
    }
    g_norms[m * KC + k] = s;
}

// Prefetch linear segment seg (128 contiguous codebook rows) into buf, swizzled.
__device__ __forceinline__ void prefetch_seg(float* buf, const float* __restrict__ cb,
                                             int seg, int tid) {
    const float* src = cb + (size_t)seg * SFLOATS;
    #pragma unroll
    for (int t = 0; t < (SFLOATS / 4) / TPB; ++t) {     // 16 iters
        int i = tid + TPB * t;                          // 16B chunk id
        int r = i >> 5, jj = i & 31;
        cp16(buf + r * DD + 4 * (jj ^ (r & 7)), src + 4 * i);
    }
    asm volatile("cp.async.commit_group;");
}

__global__ void __launch_bounds__(TPB, 1)
rq_kernel(const float* __restrict__ x, const float* __restrict__ cb,
          float* __restrict__ out_recon, float* __restrict__ out_codes,
          float* __restrict__ out_side)
{
    extern __shared__ float sm[];
    float* sB[2] = { sm, sm + SFLOATS };   // ping-pong segment buffers (swizzled)
    float* sR = sm + 2 * SFLOATS;          // [VB][RPAD] residuals
    float* sN = sR + VB * RPAD;            // [MS*KC] norms

    const int tid = threadIdx.x;
    const int tx = tid & 15;               // codeword group (0..15)
    const int ty = tid >> 4;               // vector group (0..15)
    const int vbase = blockIdx.x * VB;
    const int swz = tx & 7;

    // Kick off prefetch of segments 0 and 1 immediately.
    prefetch_seg(sB[0], cb, 0, tid);
    prefetch_seg(sB[1], cb, 1, tid);

    // ---- init: x tile -> residual smem; norms -> smem ----
    {
        const float4* xs = (const float4*)(x + (size_t)vbase * DD);
        #pragma unroll
        for (int t = 0; t < (VB * DD / 4) / TPB; ++t) {   // 16 iters
            int i = tid + TPB * t;
            int vv = i >> 5, j = i & 31;
            *(float4*)(sR + vv * RPAD + 4 * j) = xs[i];
        }
        #pragma unroll
        for (int t = 0; t < (MS * KC) / TPB; ++t)         // 8 iters
            sN[tid + TPB * t] = g_norms[tid + TPB * t];
    }

    for (int m = 0; m < MS; ++m) {
        u64 best[8];
        #pragma unroll
        for (int v = 0; v < 8; ++v) best[v] = ~0ull;

        #pragma unroll
        for (int h = 0; h < 2; ++h) {
            const int seg = m * 2 + h;
            // Drain this segment's cp.async group (leaves only seg+1 pending).
            if (seg == NSEG - 1) asm volatile("cp.async.wait_group 0;");
            else                 asm volatile("cp.async.wait_group 1;");
            __syncthreads();   // buffer visible; also orders prev epilogue sR writes

            const float* sC = sB[seg & 1];

            // ---- distance GEMM over this segment's 128 codewords ----
            u64 acc[64];
            #pragma unroll
            for (int i = 0; i < 64; ++i) acc[i] = 0ull;

            #pragma unroll 2
            for (int j = 0; j < 32; ++j) {
                ulonglong2 rr[8];
                #pragma unroll
                for (int v = 0; v < 8; ++v)
                    rr[v] = *(const ulonglong2*)(sR + (ty * 8 + v) * RPAD + 4 * j);
                const int joff = 16 * (j ^ swz);   // byte offset within a row
                #pragma unroll
                for (int kk = 0; kk < 8; ++kk) {
                    const char* base = (const char*)(sC + (tx + 16 * kk) * DD);
                    ulonglong2 cc = *(const ulonglong2*)(base + joff);
                    #pragma unroll
                    for (int v = 0; v < 8; ++v) {
                        ffma2(acc[kk * 8 + v], rr[v].x, cc.x);
                        ffma2(acc[kk * 8 + v], rr[v].y, cc.y);
                    }
                }
            }

            // ---- fold into per-thread argmin (sortable-bits key) ----
            #pragma unroll
            for (int kk = 0; kk < 8; ++kk) {
                int k = h * SROWS + tx + 16 * kk;
                float cn = sN[m * KC + k];
                #pragma unroll
                for (int v = 0; v < 8; ++v) {
                    float a, b;
                    upk2(acc[kk * 8 + v], a, b);
                    float d2v = fmaf(-2.0f, a + b, cn);
                    unsigned bits = __float_as_uint(d2v);
                    bits ^= (bits & 0x80000000u) ? 0xFFFFFFFFu : 0x80000000u;
                    u64 key = ((u64)bits << 32) | (unsigned)k;
                    if (key < best[v]) best[v] = key;
                }
            }

            __syncthreads();   // all warps done reading sC -> safe to overwrite
            if (seg + 2 < NSEG) prefetch_seg(sB[seg & 1], cb, seg + 2, tid);
        }

        // ---- butterfly min across the 16-lane tx group ----
        #pragma unroll
        for (int s = 1; s < 16; s <<= 1) {
            #pragma unroll
            for (int v = 0; v < 8; ++v) {
                u64 o = __shfl_xor_sync(0xFFFFFFFFu, best[v], s);
                if (o < best[v]) best[v] = o;
            }
        }

        // ---- epilogue: winner row read from global cb (L2-hot) ----
        #pragma unroll
        for (int v = 0; v < 8; ++v) {
            const int k = (int)(unsigned)best[v];          // low 32 bits = index
            const int vec = ty * 8 + v;
            const int gvec = vbase + vec;
            const float4* crow = (const float4*)(cb + ((size_t)m * KC + k) * DD);
            #pragma unroll
            for (int t = 0; t < 2; ++t) {
                int j = tx + 16 * t;
                float4 c = __ldg(crow + j);
                float4 r = *(const float4*)(sR + vec * RPAD + 4 * j);
                r.x -= c.x; r.y -= c.y; r.z -= c.z; r.w -= c.w;
                *(float4*)(sR + vec * RPAD + 4 * j) = r;
                float4 xv = *(const float4*)(x + (size_t)gvec * DD + 4 * j);
                float4 rec = make_float4(xv.x - r.x, xv.y - r.y, xv.z - r.z, xv.w - r.w);
                *(float4*)(out_side + ((size_t)m * NV + gvec) * DD + 4 * j) = rec;
                if (m == MS - 1)
                    *(float4*)(out_recon + (size_t)gvec * DD + 4 * j) = rec;
            }
            // one-hot codes row (zero-fill folded in)
            float4* cd = (float4*)(out_codes + (size_t)gvec * (MS * KC) + (size_t)m * KC);
            const int q = k >> 2, rsel = k & 3;
            #pragma unroll
            for (int u = 0; u < 4; ++u) {
                int g = tx + 16 * u;
                float4 vv = make_float4(0.f, 0.f, 0.f, 0.f);
                if (g == q) {
                    if      (rsel == 0) vv.x = 1.f;
                    else if (rsel == 1) vv.y = 1.f;
                    else if (rsel == 2) vv.z = 1.f;
                    else                vv.w = 1.f;
                }
                cd[g] = vv;
            }
        }
    }
}

extern "C" void kernel_launch(void* const* d_in, const int* in_sizes, int n_in,
                              void* d_out, int out_size)
{
    const float* x  = (const float*)d_in[0];   // (N, D) fp32
    const float* cb = (const float*)d_in[1];   // (M, K, D) fp32

    float* out       = (float*)d_out;
    float* out_recon = out;                                // N*D
    float* out_codes = out + (size_t)NV * DD;              // N*M*K
    float* out_side  = out_codes + (size_t)NV * MS * KC;   // M*N*D

    norms_kernel<<<MS, KC>>>(cb);
    cudaFuncSetAttribute(rq_kernel, cudaFuncAttributeMaxDynamicSharedMemorySize, SMEM_BYTES);
    rq_kernel<<<NV / VB, TPB, SMEM_BYTES>>>(x, cb, out_recon, out_codes, out_side);
}